// round 6
// baseline (speedup 1.0000x reference)
#include <cuda_runtime.h>
#include <math.h>
#include <stdint.h>

// CosineAttention: B=64, L=4096, D=1024  — single fused kernel.
//
// Grid (512, 64): each CTA = 8 warps, one warp per (b,l) key row. Streams keys
// once (1 GiB, __ldcs evict-first), computes dot(k,q) and dot(k,k) in one pass,
// writes raw score s = dot / max(||k||,eps) into d_out.
// Last-block pattern: per-batch atomic counter; the 512th CTA to finish a batch
// row performs the masked softmax for that row inline (scores are L2-hot),
// then resets the counter for graph replay. Eliminates the 2nd launch (~6us).
//
// Inputs bound BY ELEMENT COUNT: query=65536, keys=268435456, mask=262144(int32).

#define B 64
#define L 4096
#define D 1024
#define EPS 1e-12f

#define WARPS_PER_BLOCK 8
#define THREADS1 (WARPS_PER_BLOCK * 32)
#define CTAS_PER_BATCH (L / WARPS_PER_BLOCK)   // 512

__device__ int g_counters[B];   // zero-initialized at module load; last CTA resets

__global__ __launch_bounds__(THREADS1)
void cosatt_fused_kernel(const float* __restrict__ query,
                         const float* __restrict__ keys,
                         const int* __restrict__ mask,
                         float* __restrict__ out)
{
    const int b    = blockIdx.y;
    const int warp = threadIdx.x >> 5;
    const int lane = threadIdx.x & 31;
    const int tid  = threadIdx.x;
    const int l    = blockIdx.x * WARPS_PER_BLOCK + warp;

    __shared__ float red[WARPS_PER_BLOCK];
    __shared__ float s_scalar;
    __shared__ int   s_last;

    // ================= phase 1: score for this warp's key row ================
    {
        const float4* __restrict__ krow =
            reinterpret_cast<const float4*>(keys + ((size_t)b * L + l) * D);
        const float4* __restrict__ qrow =
            reinterpret_cast<const float4*>(query + (size_t)b * D);

        float dot = 0.f;
        float kk  = 0.f;

        // 256 float4 per row; 32 lanes x 8 unrolled iters -> MLP ~8 LDG.128.
        #pragma unroll
        for (int i = 0; i < 8; ++i) {
            const int idx = i * 32 + lane;
            float4 kv = __ldcs(&krow[idx]);   // touch-once stream, evict-first
            float4 qv = qrow[idx];            // L1-resident, shared by block
            dot = fmaf(kv.x, qv.x, dot);
            dot = fmaf(kv.y, qv.y, dot);
            dot = fmaf(kv.z, qv.z, dot);
            dot = fmaf(kv.w, qv.w, dot);
            kk  = fmaf(kv.x, kv.x, kk);
            kk  = fmaf(kv.y, kv.y, kk);
            kk  = fmaf(kv.z, kv.z, kk);
            kk  = fmaf(kv.w, kv.w, kk);
        }

        #pragma unroll
        for (int off = 16; off > 0; off >>= 1) {
            dot += __shfl_xor_sync(0xffffffffu, dot, off);
            kk  += __shfl_xor_sync(0xffffffffu, kk,  off);
        }

        if (lane == 0) {
            float kn = fmaxf(sqrtf(kk), EPS);
            out[(size_t)b * L + l] = dot / kn;
            __threadfence();   // make score visible device-wide before arrival
        }
    }

    __syncthreads();

    // ================= arrival: am I the last CTA for batch b? ===============
    if (tid == 0) {
        int old = atomicAdd(&g_counters[b], 1);
        s_last = (old == CTAS_PER_BATCH - 1);
        if (s_last) __threadfence();   // acquire: all scores of batch b visible
    }
    __syncthreads();
    if (!s_last) return;

    // ================= phase 2 (last CTA only): masked softmax ===============
    // 256 threads, 16 scores each. Scores were written by other SMs -> L2-hot;
    // read with __ldcg to bypass (cold/possibly-stale-free but be explicit) L1.

    // ---- ||q|| ----
    {
        const float* q = query + (size_t)b * D;
        float qq = 0.f;
        #pragma unroll
        for (int i = 0; i < D / THREADS1; ++i) {   // 4 per thread
            float v = q[i * THREADS1 + tid];
            qq = fmaf(v, v, qq);
        }
        #pragma unroll
        for (int off = 16; off > 0; off >>= 1)
            qq += __shfl_xor_sync(0xffffffffu, qq, off);
        if (lane == 0) red[warp] = qq;
        __syncthreads();
        if (tid < 32) {
            float v = (tid < WARPS_PER_BLOCK) ? red[tid] : 0.f;
            #pragma unroll
            for (int off = 16; off > 0; off >>= 1)
                v += __shfl_xor_sync(0xffffffffu, v, off);
            if (tid == 0) s_scalar = fmaxf(sqrtf(v), EPS);
        }
        __syncthreads();
    }
    const float inv_qn = 1.0f / s_scalar;

    // ---- load + scale + mask (16 per thread, float4/int4 vectorized) ----
    const float4* srow = reinterpret_cast<const float4*>(out  + (size_t)b * L);
    const int4*   mrow = reinterpret_cast<const int4*>(mask + (size_t)b * L);

    float v[16];
    float local_max = -INFINITY;
    #pragma unroll
    for (int i = 0; i < 4; ++i) {
        const int idx = i * THREADS1 + tid;
        float4 sv = __ldcg(&srow[idx]);
        int4   mv = mrow[idx];
        v[i*4+0] = mv.x ? sv.x * inv_qn : -INFINITY;
        v[i*4+1] = mv.y ? sv.y * inv_qn : -INFINITY;
        v[i*4+2] = mv.z ? sv.z * inv_qn : -INFINITY;
        v[i*4+3] = mv.w ? sv.w * inv_qn : -INFINITY;
        local_max = fmaxf(local_max, fmaxf(fmaxf(v[i*4+0], v[i*4+1]),
                                           fmaxf(v[i*4+2], v[i*4+3])));
    }

    // ---- block max ----
    #pragma unroll
    for (int off = 16; off > 0; off >>= 1)
        local_max = fmaxf(local_max, __shfl_xor_sync(0xffffffffu, local_max, off));
    __syncthreads();  // red[] reuse
    if (lane == 0) red[warp] = local_max;
    __syncthreads();
    if (tid < 32) {
        float m = (tid < WARPS_PER_BLOCK) ? red[tid] : -INFINITY;
        #pragma unroll
        for (int off = 16; off > 0; off >>= 1)
            m = fmaxf(m, __shfl_xor_sync(0xffffffffu, m, off));
        if (tid == 0) s_scalar = m;
    }
    __syncthreads();
    const float row_max = s_scalar;

    // ---- exp + block sum ----
    float local_sum = 0.f;
    #pragma unroll
    for (int i = 0; i < 16; ++i) {
        float e = __expf(v[i] - row_max);   // exp(-inf - m) = 0 for masked
        v[i] = e;
        local_sum += e;
    }
    #pragma unroll
    for (int off = 16; off > 0; off >>= 1)
        local_sum += __shfl_xor_sync(0xffffffffu, local_sum, off);
    __syncthreads();
    if (lane == 0) red[warp] = local_sum;
    __syncthreads();
    if (tid < 32) {
        float sm = (tid < WARPS_PER_BLOCK) ? red[tid] : 0.f;
        #pragma unroll
        for (int off = 16; off > 0; off >>= 1)
            sm += __shfl_xor_sync(0xffffffffu, sm, off);
        if (tid == 0) s_scalar = sm;
    }
    __syncthreads();
    const float inv_sum = 1.0f / s_scalar;

    // ---- write normalized probs ----
    float4* orow = reinterpret_cast<float4*>(out + (size_t)b * L);
    #pragma unroll
    for (int i = 0; i < 4; ++i) {
        const int idx = i * THREADS1 + tid;
        float4 o;
        o.x = v[i*4+0] * inv_sum;
        o.y = v[i*4+1] * inv_sum;
        o.z = v[i*4+2] * inv_sum;
        o.w = v[i*4+3] * inv_sum;
        orow[idx] = o;
    }

    // reset counter for the next graph replay (all CTAs of this batch arrived)
    if (tid == 0) g_counters[b] = 0;
}

extern "C" void kernel_launch(void* const* d_in, const int* in_sizes, int n_in,
                              void* d_out, int out_size)
{
    const float* query = nullptr;  // B*D   = 65536
    const float* keys  = nullptr;  // B*L*D = 268435456
    const int*   mask  = nullptr;  // B*L   = 262144 (int32)

    for (int i = 0; i < n_in; ++i) {
        if (in_sizes[i] == B * D)      query = (const float*)d_in[i];
        else if (in_sizes[i] == B * L) mask  = (const int*)d_in[i];
        else                           keys  = (const float*)d_in[i];
    }

    float* out = (float*)d_out;  // [B, L] float32

    dim3 grid(CTAS_PER_BATCH, B);
    cosatt_fused_kernel<<<grid, THREADS1>>>(query, keys, mask, out);
}

// round 7
// speedup vs baseline: 1.2882x; 1.2882x over previous
#include <cuda_runtime.h>
#include <math.h>
#include <stdint.h>

// CosineAttention: B=64, L=4096, D=1024
//   q = l2norm(query); k = l2norm(keys); scores = k @ q; softmax over L + mask.
//
// Kernel 1: 2 key rows per warp (16 independent DRAM LDG.128 in flight per
//           warp). Streams keys once (1 GiB, __ldcs evict-first), computes
//           dot(k,q) and dot(k,k) per row, writes s = dot/max(||k||,eps).
// Kernel 2: one 1024-thread block per batch row; ||q||, scale, mask(int32),
//           softmax in-place. (Fusing these regressed 33% in R6 — the extra
//           control flow degraded the streaming loop's MLP; keep separate.)
//
// Inputs bound BY ELEMENT COUNT: query=65536, keys=268435456, mask=262144(int32).

#define B 64
#define L 4096
#define D 1024
#define EPS 1e-12f

#define WARPS_PER_BLOCK 8
#define ROWS_PER_WARP 2
#define THREADS1 (WARPS_PER_BLOCK * 32)
#define ROWS_PER_CTA (WARPS_PER_BLOCK * ROWS_PER_WARP)   // 16

__global__ __launch_bounds__(THREADS1)
void cosatt_scores_kernel(const float* __restrict__ query,
                          const float* __restrict__ keys,
                          float* __restrict__ scores)
{
    const int b    = blockIdx.y;
    const int warp = threadIdx.x >> 5;
    const int lane = threadIdx.x & 31;
    const int l0   = (blockIdx.x * WARPS_PER_BLOCK + warp) * ROWS_PER_WARP;

    const float4* __restrict__ krow0 =
        reinterpret_cast<const float4*>(keys + ((size_t)b * L + l0) * D);
    const float4* __restrict__ krow1 = krow0 + (D / 4);
    const float4* __restrict__ qrow =
        reinterpret_cast<const float4*>(query + (size_t)b * D);

    float dot0 = 0.f, kk0 = 0.f;
    float dot1 = 0.f, kk1 = 0.f;

    // 256 float4 per row; 32 lanes x 8 unrolled iters x 2 rows ->
    // 16 independent DRAM LDG.128 per lane in flight (+8 L1-hit q loads).
    #pragma unroll
    for (int i = 0; i < 8; ++i) {
        const int idx = i * 32 + lane;
        float4 qv = qrow[idx];              // L1-resident, shared by block
        float4 k0 = __ldcs(&krow0[idx]);    // touch-once stream, evict-first
        float4 k1 = __ldcs(&krow1[idx]);
        dot0 = fmaf(k0.x, qv.x, dot0);
        dot0 = fmaf(k0.y, qv.y, dot0);
        dot0 = fmaf(k0.z, qv.z, dot0);
        dot0 = fmaf(k0.w, qv.w, dot0);
        kk0  = fmaf(k0.x, k0.x, kk0);
        kk0  = fmaf(k0.y, k0.y, kk0);
        kk0  = fmaf(k0.z, k0.z, kk0);
        kk0  = fmaf(k0.w, k0.w, kk0);
        dot1 = fmaf(k1.x, qv.x, dot1);
        dot1 = fmaf(k1.y, qv.y, dot1);
        dot1 = fmaf(k1.z, qv.z, dot1);
        dot1 = fmaf(k1.w, qv.w, dot1);
        kk1  = fmaf(k1.x, k1.x, kk1);
        kk1  = fmaf(k1.y, k1.y, kk1);
        kk1  = fmaf(k1.z, k1.z, kk1);
        kk1  = fmaf(k1.w, k1.w, kk1);
    }

    #pragma unroll
    for (int off = 16; off > 0; off >>= 1) {
        dot0 += __shfl_xor_sync(0xffffffffu, dot0, off);
        kk0  += __shfl_xor_sync(0xffffffffu, kk0,  off);
        dot1 += __shfl_xor_sync(0xffffffffu, dot1, off);
        kk1  += __shfl_xor_sync(0xffffffffu, kk1,  off);
    }

    if (lane == 0) {
        scores[(size_t)b * L + l0]     = dot0 / fmaxf(sqrtf(kk0), EPS);
        scores[(size_t)b * L + l0 + 1] = dot1 / fmaxf(sqrtf(kk1), EPS);
    }
}

#define THREADS2 1024
#define NWARP2 (THREADS2 / 32)

__global__ __launch_bounds__(THREADS2)
void cosatt_softmax_kernel(const float* __restrict__ query,
                           const int* __restrict__ mask,
                           float* __restrict__ scores /* in/out */)
{
    const int b   = blockIdx.x;
    const int tid = threadIdx.x;

    __shared__ float red[NWARP2];
    __shared__ float s_qn, s_max, s_sum;

    // ---- ||q|| : 1024 elems, 1 per thread ----
    {
        float qv = query[(size_t)b * D + tid];
        float qq = qv * qv;
        #pragma unroll
        for (int off = 16; off > 0; off >>= 1)
            qq += __shfl_xor_sync(0xffffffffu, qq, off);
        if ((tid & 31) == 0) red[tid >> 5] = qq;
        __syncthreads();
        if (tid < 32) {
            float v = (tid < NWARP2) ? red[tid] : 0.f;
            #pragma unroll
            for (int off = 16; off > 0; off >>= 1)
                v += __shfl_xor_sync(0xffffffffu, v, off);
            if (tid == 0) s_qn = fmaxf(sqrtf(v), EPS);
        }
        __syncthreads();
    }
    const float inv_qn = 1.0f / s_qn;

    // ---- load 4 scores + 4 mask vals per thread (vectorized) ----
    const float4* srow = reinterpret_cast<const float4*>(scores + (size_t)b * L);
    const int4*   mrow = reinterpret_cast<const int4*>(mask + (size_t)b * L);

    float4 sv = srow[tid];
    int4   mv = mrow[tid];

    float v0 = mv.x ? sv.x * inv_qn : -INFINITY;
    float v1 = mv.y ? sv.y * inv_qn : -INFINITY;
    float v2 = mv.z ? sv.z * inv_qn : -INFINITY;
    float v3 = mv.w ? sv.w * inv_qn : -INFINITY;

    // ---- block max ----
    float m = fmaxf(fmaxf(v0, v1), fmaxf(v2, v3));
    #pragma unroll
    for (int off = 16; off > 0; off >>= 1)
        m = fmaxf(m, __shfl_xor_sync(0xffffffffu, m, off));
    if ((tid & 31) == 0) red[tid >> 5] = m;
    __syncthreads();
    if (tid < 32) {
        float t = (tid < NWARP2) ? red[tid] : -INFINITY;
        #pragma unroll
        for (int off = 16; off > 0; off >>= 1)
            t = fmaxf(t, __shfl_xor_sync(0xffffffffu, t, off));
        if (tid == 0) s_max = t;
    }
    __syncthreads();
    const float row_max = s_max;

    // ---- exp + block sum ----
    v0 = __expf(v0 - row_max);
    v1 = __expf(v1 - row_max);
    v2 = __expf(v2 - row_max);
    v3 = __expf(v3 - row_max);
    float sum = (v0 + v1) + (v2 + v3);
    #pragma unroll
    for (int off = 16; off > 0; off >>= 1)
        sum += __shfl_xor_sync(0xffffffffu, sum, off);
    __syncthreads();   // safe reuse of red[]
    if ((tid & 31) == 0) red[tid >> 5] = sum;
    __syncthreads();
    if (tid < 32) {
        float t = (tid < NWARP2) ? red[tid] : 0.f;
        #pragma unroll
        for (int off = 16; off > 0; off >>= 1)
            t += __shfl_xor_sync(0xffffffffu, t, off);
        if (tid == 0) s_sum = t;
    }
    __syncthreads();
    const float inv_sum = 1.0f / s_sum;

    float4 o;
    o.x = v0 * inv_sum;
    o.y = v1 * inv_sum;
    o.z = v2 * inv_sum;
    o.w = v3 * inv_sum;
    reinterpret_cast<float4*>(scores + (size_t)b * L)[tid] = o;
}

extern "C" void kernel_launch(void* const* d_in, const int* in_sizes, int n_in,
                              void* d_out, int out_size)
{
    const float* query = nullptr;  // B*D   = 65536
    const float* keys  = nullptr;  // B*L*D = 268435456
    const int*   mask  = nullptr;  // B*L   = 262144 (int32)

    for (int i = 0; i < n_in; ++i) {
        if (in_sizes[i] == B * D)      query = (const float*)d_in[i];
        else if (in_sizes[i] == B * L) mask  = (const int*)d_in[i];
        else                           keys  = (const float*)d_in[i];
    }

    float* out = (float*)d_out;  // [B, L] float32

    dim3 grid1(L / ROWS_PER_CTA, B);
    cosatt_scores_kernel<<<grid1, THREADS1>>>(query, keys, out);
    cosatt_softmax_kernel<<<B, THREADS2>>>(query, mask, out);
}

// round 8
// speedup vs baseline: 1.3562x; 1.0528x over previous
#include <cuda_runtime.h>
#include <math.h>
#include <stdint.h>

// CosineAttention: B=64, L=4096, D=1024
//   q = l2norm(query); k = l2norm(keys); scores = k @ q; softmax over L + mask.
//
// Kernel 1: one warp per (b,l) key row (R5 structure — best measured, MLP 8 at
//           the DRAM ceiling). Also accumulates q.q (q is L1-resident) and
//           writes the FINISHED cosine s = dot / (max(||k||,eps)*max(||q||,eps)).
// Kernel 2: one 1024-thread block per batch row. Since s in [-1,1], softmax
//           needs no max-subtraction (shift-invariant, no overflow): just
//           exp, one sum-reduction, scale. Single block reduction total.
//
// Inputs bound BY ELEMENT COUNT: query=65536, keys=268435456, mask=262144(int32).

#define B 64
#define L 4096
#define D 1024
#define EPS 1e-12f

#define WARPS_PER_BLOCK 8
#define THREADS1 (WARPS_PER_BLOCK * 32)

__global__ __launch_bounds__(THREADS1)
void cosatt_scores_kernel(const float* __restrict__ query,
                          const float* __restrict__ keys,
                          float* __restrict__ scores)
{
    const int b    = blockIdx.y;
    const int warp = threadIdx.x >> 5;
    const int lane = threadIdx.x & 31;
    const int l    = blockIdx.x * WARPS_PER_BLOCK + warp;

    const float4* __restrict__ krow =
        reinterpret_cast<const float4*>(keys + ((size_t)b * L + l) * D);
    const float4* __restrict__ qrow =
        reinterpret_cast<const float4*>(query + (size_t)b * D);

    float dot = 0.f;
    float kk  = 0.f;
    float qq  = 0.f;

    // 256 float4 per row; 32 lanes x 8 unrolled iters -> MLP ~8 LDG.128.
    #pragma unroll
    for (int i = 0; i < 8; ++i) {
        const int idx = i * 32 + lane;
        float4 kv = __ldcs(&krow[idx]);   // touch-once stream, evict-first
        float4 qv = qrow[idx];            // L1-resident, shared by block
        dot = fmaf(kv.x, qv.x, dot);
        dot = fmaf(kv.y, qv.y, dot);
        dot = fmaf(kv.z, qv.z, dot);
        dot = fmaf(kv.w, qv.w, dot);
        kk  = fmaf(kv.x, kv.x, kk);
        kk  = fmaf(kv.y, kv.y, kk);
        kk  = fmaf(kv.z, kv.z, kk);
        kk  = fmaf(kv.w, kv.w, kk);
        qq  = fmaf(qv.x, qv.x, qq);
        qq  = fmaf(qv.y, qv.y, qq);
        qq  = fmaf(qv.z, qv.z, qq);
        qq  = fmaf(qv.w, qv.w, qq);
    }

    #pragma unroll
    for (int off = 16; off > 0; off >>= 1) {
        dot += __shfl_xor_sync(0xffffffffu, dot, off);
        kk  += __shfl_xor_sync(0xffffffffu, kk,  off);
        qq  += __shfl_xor_sync(0xffffffffu, qq,  off);
    }

    if (lane == 0) {
        float kn = fmaxf(sqrtf(kk), EPS);
        float qn = fmaxf(sqrtf(qq), EPS);
        scores[(size_t)b * L + l] = dot / (kn * qn);
    }
}

#define THREADS2 1024
#define NWARP2 (THREADS2 / 32)

__global__ __launch_bounds__(THREADS2)
void cosatt_softmax_kernel(const int* __restrict__ mask,
                           float* __restrict__ scores /* in/out */)
{
    const int b   = blockIdx.x;
    const int tid = threadIdx.x;

    __shared__ float red[NWARP2];
    __shared__ float s_sum;

    // scores are finished cosines in [-1,1]: softmax needs no max shift.
    const float4* srow = reinterpret_cast<const float4*>(scores + (size_t)b * L);
    const int4*   mrow = reinterpret_cast<const int4*>(mask + (size_t)b * L);

    float4 sv = srow[tid];
    int4   mv = mrow[tid];

    float v0 = mv.x ? __expf(sv.x) : 0.f;
    float v1 = mv.y ? __expf(sv.y) : 0.f;
    float v2 = mv.z ? __expf(sv.z) : 0.f;
    float v3 = mv.w ? __expf(sv.w) : 0.f;

    float sum = (v0 + v1) + (v2 + v3);
    #pragma unroll
    for (int off = 16; off > 0; off >>= 1)
        sum += __shfl_xor_sync(0xffffffffu, sum, off);
    if ((tid & 31) == 0) red[tid >> 5] = sum;
    __syncthreads();
    if (tid < 32) {
        float t = (tid < NWARP2) ? red[tid] : 0.f;
        #pragma unroll
        for (int off = 16; off > 0; off >>= 1)
            t += __shfl_xor_sync(0xffffffffu, t, off);
        if (tid == 0) s_sum = t;
    }
    __syncthreads();
    const float inv_sum = 1.0f / s_sum;

    float4 o;
    o.x = v0 * inv_sum;
    o.y = v1 * inv_sum;
    o.z = v2 * inv_sum;
    o.w = v3 * inv_sum;
    reinterpret_cast<float4*>(scores + (size_t)b * L)[tid] = o;
}

extern "C" void kernel_launch(void* const* d_in, const int* in_sizes, int n_in,
                              void* d_out, int out_size)
{
    const float* query = nullptr;  // B*D   = 65536
    const float* keys  = nullptr;  // B*L*D = 268435456
    const int*   mask  = nullptr;  // B*L   = 262144 (int32)

    for (int i = 0; i < n_in; ++i) {
        if (in_sizes[i] == B * D)      query = (const float*)d_in[i];
        else if (in_sizes[i] == B * L) mask  = (const int*)d_in[i];
        else                           keys  = (const float*)d_in[i];
    }

    float* out = (float*)d_out;  // [B, L] float32

    dim3 grid1(L / WARPS_PER_BLOCK, B);
    cosatt_scores_kernel<<<grid1, THREADS1>>>(query, keys, out);
    cosatt_softmax_kernel<<<B, THREADS2>>>(mask, out);
}